// round 3
// baseline (speedup 1.0000x reference)
#include <cuda_runtime.h>
#include <cuda_bf16.h>

// Problem constants (fixed shapes from reference setup_inputs)
#define BB 4
#define NN 16384
#define PP 1024
#define CC 128
#define NS 64
#define R2 0.04f
#define FST 65   // ftile row stride (odd -> conflict-free column STS in phase 2)

// Scratch (allocations forbidden; __device__ global)
__device__ float g_ftrans[(size_t)BB * NN * CC];   // (B, N, C), 32 MB

// ---------------------------------------------------------------------------
// Kernel A: transpose features (B, C, N) -> (B, N, C)
// ---------------------------------------------------------------------------
__global__ void transpose_kernel(const float* __restrict__ f) {
    __shared__ float tile[32][33];
    const int b = blockIdx.z;
    const int nBase = blockIdx.x * 32;
    const int cBase = blockIdx.y * 32;
    const float* fb = f + (size_t)b * CC * NN;
    float* ob = g_ftrans + (size_t)b * NN * CC;
    const int tx = threadIdx.x, ty = threadIdx.y;  // 32 x 8
#pragma unroll
    for (int i = 0; i < 32; i += 8)
        tile[ty + i][tx] = fb[(size_t)(cBase + ty + i) * NN + nBase + tx];
    __syncthreads();
#pragma unroll
    for (int i = 0; i < 32; i += 8)
        ob[(size_t)(nBase + ty + i) * CC + cBase + tx] = tile[tx][ty + i];
}

// ---------------------------------------------------------------------------
// Kernel B (fused): block per (b, p).
//   Phase 1: ordered ball-query compaction, 1024 pts/iter, 1 barrier/iter.
//   Phase 2: gather feature rows into smem tile [ch][s] (stride 65).
//   Phase 3: STG.128 channel-major output along s; xyz channels scalar.
// ---------------------------------------------------------------------------
__global__ void __launch_bounds__(256) fused_kernel(
    const float* __restrict__ xyz, const float* __restrict__ new_xyz,
    float* __restrict__ out) {
    __shared__ float ftile[CC * FST];   // 33280 B
    __shared__ int sidx[NS];
    __shared__ int smidx[NS];
    __shared__ unsigned wcnt[2][8];     // double-buffered packed per-warp counts

    const int p = blockIdx.x;
    const int b = blockIdx.y;
    const int t = threadIdx.x;
    const int warp = t >> 5;
    const int lane = t & 31;

    const float qx = new_xyz[((size_t)b * PP + p) * 3 + 0];
    const float qy = new_xyz[((size_t)b * PP + p) * 3 + 1];
    const float qz = new_xyz[((size_t)b * PP + p) * 3 + 2];
    const float* xb = xyz + (size_t)b * NN * 3;

    // ---- Phase 1: ordered compaction, 1024 points / iteration ----
    int cnt = 0;
    int sel = 0;
    for (int base = 0; base < NN; base += 1024) {
        float px[4], py[4], pz[4];
#pragma unroll
        for (int u = 0; u < 4; u++) {   // strided sub-chunks: order = (u, t)
            const int i = base + u * 256 + t;
            px[u] = xb[i * 3 + 0];
            py[u] = xb[i * 3 + 1];
            pz[u] = xb[i * 3 + 2];
        }
        unsigned m[4];
        int hit[4];
        unsigned packed = 0;
#pragma unroll
        for (int u = 0; u < 4; u++) {
            // Match JAX f32 rounding: no FMA contraction, left-to-right sum.
            const float dx = __fadd_rn(qx, -px[u]);
            const float dy = __fadd_rn(qy, -py[u]);
            const float dz = __fadd_rn(qz, -pz[u]);
            const float d2 = __fadd_rn(__fadd_rn(__fmul_rn(dx, dx), __fmul_rn(dy, dy)),
                                       __fmul_rn(dz, dz));
            hit[u] = d2 < R2;
            m[u] = __ballot_sync(0xffffffffu, hit[u]);
            packed |= (unsigned)__popc(m[u]) << (8 * u);
        }
        if (lane == 0) wcnt[sel][warp] = packed;
        __syncthreads();   // the ONLY barrier per iteration (double-buffered wcnt)

        unsigned pk[8];
#pragma unroll
        for (int w = 0; w < 8; w++) pk[w] = wcnt[sel][w];

        int run = cnt;
#pragma unroll
        for (int u = 0; u < 4; u++) {
            int pre = run;
#pragma unroll
            for (int w = 0; w < 8; w++) {
                const int c = (pk[w] >> (8 * u)) & 0xff;
                if (w < warp) pre += c;
                run += c;
            }
            const int pos = pre + __popc(m[u] & ((1u << lane) - 1u));
            if (hit[u] && pos < NS) sidx[pos] = base + u * 256 + t;
        }
        cnt = run;          // uniform across block
        sel ^= 1;
        if (cnt >= NS) break;
    }
    __syncthreads();        // sidx visible to all
    const int cn = cnt < NS ? cnt : NS;

    // ---- idx output + masked gather indices ----
    float* out_idx = out + (size_t)BB * 131 * PP * NS + (size_t)BB * 3 * PP * NS;
    if (t < NS) {
        const int first = (cn > 0) ? sidx[0] : NN;
        const bool real = (t < cn);
        const int v0 = real ? sidx[t] : first;   // idx0 (pad -> first)
        smidx[t] = real ? sidx[t] : NN;          // masked (pad -> NN)
        out_idx[((size_t)b * PP + p) * NS + t] = (float)v0;
    }
    __syncthreads();

    // ---- Phase 2: gather 64 x 512B contiguous rows into ftile[ch][s] ----
    const float* fb = g_ftrans + (size_t)b * NN * CC;
    for (int s = warp; s < NS; s += 8) {
        const int n = smidx[s];
        if (n < NN) {
            const float* row = fb + (size_t)n * CC + lane;
#pragma unroll
            for (int j = 0; j < 4; j++)
                ftile[(lane + 32 * j) * FST + s] = row[32 * j];
        } else {
#pragma unroll
            for (int j = 0; j < 4; j++)
                ftile[(lane + 32 * j) * FST + s] = 0.0f;
        }
    }
    __syncthreads();

    // ---- Phase 3a: feature channels 3..130, STG.128 along s ----
    // Warp = 8 channels x 4 consecutive s4-groups: 64B-contiguous stores per
    // channel (sector-perfect), 2-way max LDS bank conflicts.
    float* nfb = out + (((size_t)b * 131 + 3) * PP + p) * NS;
#pragma unroll
    for (int k = 0; k < 8; k++) {
        const int ch = (t >> 2) + ((k & 1) << 6);        // 0..127
        const int s4 = (t & 3) + ((k >> 1) << 2);        // 0..15
        const float* src = &ftile[ch * FST + s4 * 4];
        const float4 v = make_float4(src[0], src[1], src[2], src[3]);
        *(float4*)&nfb[(size_t)ch * PP * NS + s4 * 4] = v;
    }

    // ---- Phase 3b: grouped_xyz + xyz_feature channels ----
    if (t < 192) {
        const int s = t & 63;
        const int c = t >> 6;   // 0..2
        const int n = smidx[s];
        const float q = (c == 0) ? qx : ((c == 1) ? qy : qz);
        const float src = (n < NN) ? xb[n * 3 + c] : 1000000.0f;
        const float g = __fadd_rn(src, -q);
        float* gx = out + (size_t)BB * 131 * PP * NS;
        gx[(((size_t)b * 3 + c) * PP + p) * NS + s] = g;
        const float xf = (g > 100000.0f) ? 0.0f : g;
        out[(((size_t)b * 131 + c) * PP + p) * NS + s] = xf / 0.2f;
    }
}

// ---------------------------------------------------------------------------
extern "C" void kernel_launch(void* const* d_in, const int* in_sizes, int n_in,
                              void* d_out, int out_size) {
    const float* xyz      = (const float*)d_in[0];  // (B, N, 3)
    const float* new_xyz  = (const float*)d_in[1];  // (B, P, 3)
    const float* features = (const float*)d_in[2];  // (B, C, N)
    float* out = (float*)d_out;

    transpose_kernel<<<dim3(NN / 32, CC / 32, BB), dim3(32, 8)>>>(features);
    fused_kernel<<<dim3(PP, BB), 256>>>(xyz, new_xyz, out);
}

// round 4
// speedup vs baseline: 1.0573x; 1.0573x over previous
#include <cuda_runtime.h>
#include <cuda_bf16.h>

// Problem constants (fixed shapes from reference setup_inputs)
#define BB 4
#define NN 16384
#define PP 1024
#define CC 128
#define NS 64
#define R2 0.04f
#define FST 65   // ftile row stride (odd -> conflict-free column STS)

// Scratch (allocations forbidden; __device__ globals)
__device__ float g_ftrans[(size_t)BB * NN * CC];   // (B, N, C), 32 MB
__device__ int   g_idx[BB * PP * NS];              // masked gather indices

// ---------------------------------------------------------------------------
// Kernel 1 (union grid): blocks [0,512) = ball query (warp per center, no
// block barriers); blocks [512, 8704) = feature transpose (B,C,N)->(B,N,C).
// Query blocks are scheduled first so their latency tail hides under the
// bandwidth-bound transpose.
// ---------------------------------------------------------------------------
__global__ void __launch_bounds__(256) prep_kernel(
    const float* __restrict__ f, const float* __restrict__ xyz,
    const float* __restrict__ new_xyz, float* __restrict__ out) {
    const int bi = blockIdx.x;
    if (bi < 512) {
        // ---------------- ball query: warp per center ----------------
        __shared__ int sidx[8][NS];
        const int warp = threadIdx.x >> 5;
        const int lane = threadIdx.x & 31;
        const int pb = bi * 8 + warp;          // 0..4095
        const int b = pb >> 10;
        const int p = pb & 1023;

        const float* xb = xyz + (size_t)b * NN * 3;
        const float qx = new_xyz[((size_t)b * PP + p) * 3 + 0];
        const float qy = new_xyz[((size_t)b * PP + p) * 3 + 1];
        const float qz = new_xyz[((size_t)b * PP + p) * 3 + 2];

        int cnt = 0;
        for (int base = 0; base < NN && cnt < NS; base += 256) {
            float px[8], py[8], pz[8];
#pragma unroll
            for (int u = 0; u < 8; u++) {      // prefetch: MLP = 24
                const int i = base + u * 32 + lane;
                px[u] = xb[i * 3 + 0];
                py[u] = xb[i * 3 + 1];
                pz[u] = xb[i * 3 + 2];
            }
#pragma unroll
            for (int u = 0; u < 8; u++) {
                // Match JAX f32 rounding: no FMA contraction, L-to-R sum.
                const float dx = __fadd_rn(qx, -px[u]);
                const float dy = __fadd_rn(qy, -py[u]);
                const float dz = __fadd_rn(qz, -pz[u]);
                const float d2 = __fadd_rn(
                    __fadd_rn(__fmul_rn(dx, dx), __fmul_rn(dy, dy)),
                    __fmul_rn(dz, dz));
                const bool hit = d2 < R2;
                const unsigned m = __ballot_sync(0xffffffffu, hit);
                const int pos = cnt + __popc(m & ((1u << lane) - 1u));
                if (hit && pos < NS) sidx[warp][pos] = base + u * 32 + lane;
                cnt += __popc(m);
            }
        }
        __syncwarp();
        const int cn = cnt < NS ? cnt : NS;
        const int first = (cn > 0) ? sidx[warp][0] : NN;
        float* out_idx = out + (size_t)BB * 131 * PP * NS + (size_t)BB * 3 * PP * NS;
        const size_t o = ((size_t)b * PP + p) * NS;
#pragma unroll
        for (int s = lane; s < NS; s += 32) {
            const bool real = (s < cn);
            const int v = real ? sidx[warp][s] : NN;
            g_idx[o + s] = v;                              // masked (pad -> NN)
            out_idx[o + s] = (float)(real ? v : first);    // idx0 (pad -> first)
        }
    } else {
        // ---------------- transpose (B,C,N) -> (B,N,C) ----------------
        __shared__ float tile[32][33];
        const int bi2 = bi - 512;
        const int b = bi2 >> 11;          // 2048 blocks per batch
        const int rem = bi2 & 2047;
        const int nBase = (rem >> 2) * 32;
        const int cBase = (rem & 3) * 32;
        const float* fb = f + (size_t)b * CC * NN;
        float* ob = g_ftrans + (size_t)b * NN * CC;
        const int tx = threadIdx.x & 31, ty = threadIdx.x >> 5;  // 32 x 8
#pragma unroll
        for (int i = 0; i < 32; i += 8)
            tile[ty + i][tx] = fb[(size_t)(cBase + ty + i) * NN + nBase + tx];
        __syncthreads();
#pragma unroll
        for (int i = 0; i < 32; i += 8)
            ob[(size_t)(nBase + ty + i) * CC + cBase + tx] = tile[tx][ty + i];
    }
}

// ---------------------------------------------------------------------------
// Kernel 2: gather + group. Block per (chunk-of-64-channels, p, b).
//   Stage 64 s-rows x 64 channels in smem [ch][s] (stride 65), then write
//   channel-major s-coalesced STG.128. chunk 0 also writes xyz channels.
// ---------------------------------------------------------------------------
__global__ void __launch_bounds__(256, 8) gather_kernel(
    const float* __restrict__ xyz, const float* __restrict__ new_xyz,
    float* __restrict__ out) {
    __shared__ float ftile[64 * FST];   // 16.6 KB
    __shared__ int smidx[NS];

    const int chunk = blockIdx.x;       // 0 / 1
    const int p = blockIdx.y;
    const int b = blockIdx.z;
    const int t = threadIdx.x;
    const int warp = t >> 5;
    const int lane = t & 31;

    if (t < NS) smidx[t] = g_idx[((size_t)b * PP + p) * NS + t];
    __syncthreads();

    // gather: 64 rows x 256B contiguous (this chunk's half of each row)
    const float* fb = g_ftrans + (size_t)b * NN * CC + chunk * 64;
#pragma unroll
    for (int s = warp; s < NS; s += 8) {
        const int n = smidx[s];
        if (n < NN) {
            const float* row = fb + (size_t)n * CC + lane;
            ftile[lane * FST + s] = row[0];
            ftile[(lane + 32) * FST + s] = row[32];
        } else {
            ftile[lane * FST + s] = 0.0f;
            ftile[(lane + 32) * FST + s] = 0.0f;
        }
    }
    __syncthreads();

    // write: 64 channels x 64 s, STG.128 along s (256B contiguous per ch/warp)
    float* nfb = out + (((size_t)b * 131 + 3 + chunk * 64) * PP + p) * NS;
#pragma unroll
    for (int k = 0; k < 4; k++) {
        const int idx = t + 256 * k;     // 0..1023
        const int ch = idx >> 4;         // 0..63
        const int s4 = idx & 15;         // 0..15
        const float* src = &ftile[ch * FST + s4 * 4];
        const float4 v = make_float4(src[0], src[1], src[2], src[3]);
        *(float4*)&nfb[(size_t)ch * PP * NS + s4 * 4] = v;
    }

    // xyz channels: grouped_xyz + xyz_feature (chunk 0 only)
    if (chunk == 0 && t < 192) {
        const int s = t & 63;
        const int c = t >> 6;   // 0..2
        const int n = smidx[s];
        const float q = new_xyz[((size_t)b * PP + p) * 3 + c];
        const float src = (n < NN) ? xyz[((size_t)b * NN + n) * 3 + c] : 1000000.0f;
        const float g = __fadd_rn(src, -q);
        float* gx = out + (size_t)BB * 131 * PP * NS;
        gx[(((size_t)b * 3 + c) * PP + p) * NS + s] = g;
        const float xf = (g > 100000.0f) ? 0.0f : g;
        out[(((size_t)b * 131 + c) * PP + p) * NS + s] = xf / 0.2f;
    }
}

// ---------------------------------------------------------------------------
extern "C" void kernel_launch(void* const* d_in, const int* in_sizes, int n_in,
                              void* d_out, int out_size) {
    const float* xyz      = (const float*)d_in[0];  // (B, N, 3)
    const float* new_xyz  = (const float*)d_in[1];  // (B, P, 3)
    const float* features = (const float*)d_in[2];  // (B, C, N)
    float* out = (float*)d_out;

    prep_kernel<<<512 + 8192, 256>>>(features, xyz, new_xyz, out);
    gather_kernel<<<dim3(2, PP, BB), 256>>>(xyz, new_xyz, out);
}

// round 5
// speedup vs baseline: 1.4034x; 1.3273x over previous
#include <cuda_runtime.h>
#include <cuda_bf16.h>

// Problem constants (fixed shapes from reference setup_inputs)
#define BB 4
#define NN 16384
#define PP 1024
#define CC 128
#define NS 64
#define R2 0.04f
#define FST 65   // ftile row stride (odd -> conflict-free column STS)

#define NQBLK (BB * PP)       // 4096 query blocks
#define NTBLK (BB * 512 * 4)  // 8192 transpose blocks

// Scratch (allocations forbidden; __device__ globals)
__device__ float g_ftrans[(size_t)BB * NN * CC];   // (B, N, C), 32 MB
__device__ int   g_idx[BB * PP * NS];              // masked gather indices

// ---------------------------------------------------------------------------
// Kernel 1 (union grid): blocks [0, NQBLK) = ball query, block per center,
// 512 pts/iter, ONE barrier/iter (double-buffered counts), prefetched loads.
// Blocks [NQBLK, NQBLK+NTBLK) = feature transpose (B,C,N) -> (B,N,C).
// ---------------------------------------------------------------------------
__global__ void __launch_bounds__(256) prep_kernel(
    const float* __restrict__ f, const float* __restrict__ xyz,
    const float* __restrict__ new_xyz, float* __restrict__ out) {
    const int bi = blockIdx.x;
    const int t = threadIdx.x;
    if (bi < NQBLK) {
        // ---------------- ball query: block per center ----------------
        __shared__ int sidx[NS];
        __shared__ unsigned wcnt[2][8];
        const int b = bi >> 10;
        const int p = bi & 1023;
        const int warp = t >> 5;
        const int lane = t & 31;

        const float* xb = xyz + (size_t)b * NN * 3;
        const float qx = new_xyz[((size_t)b * PP + p) * 3 + 0];
        const float qy = new_xyz[((size_t)b * PP + p) * 3 + 1];
        const float qz = new_xyz[((size_t)b * PP + p) * 3 + 2];

        // prefetch chunk 0 (each thread owns points t and t+256 of the chunk)
        float x0 = xb[t * 3 + 0], y0 = xb[t * 3 + 1], z0 = xb[t * 3 + 2];
        float x1 = xb[(t + 256) * 3 + 0], y1 = xb[(t + 256) * 3 + 1],
              z1 = xb[(t + 256) * 3 + 2];

        int cnt = 0, sel = 0;
        for (int base = 0; base < NN; base += 512) {
            // hits for current chunk (JAX f32 rounding: no FMA, L-to-R sum)
            const float dx0 = __fadd_rn(qx, -x0), dy0 = __fadd_rn(qy, -y0),
                        dz0 = __fadd_rn(qz, -z0);
            const float d20 = __fadd_rn(
                __fadd_rn(__fmul_rn(dx0, dx0), __fmul_rn(dy0, dy0)),
                __fmul_rn(dz0, dz0));
            const float dx1 = __fadd_rn(qx, -x1), dy1 = __fadd_rn(qy, -y1),
                        dz1 = __fadd_rn(qz, -z1);
            const float d21 = __fadd_rn(
                __fadd_rn(__fmul_rn(dx1, dx1), __fmul_rn(dy1, dy1)),
                __fmul_rn(dz1, dz1));
            const bool h0 = d20 < R2;
            const bool h1 = d21 < R2;
            const unsigned m0 = __ballot_sync(0xffffffffu, h0);
            const unsigned m1 = __ballot_sync(0xffffffffu, h1);
            if (lane == 0)
                wcnt[sel][warp] = (unsigned)__popc(m0) | ((unsigned)__popc(m1) << 8);

            // prefetch next chunk BEFORE the barrier (coords no longer needed)
            const int nb = base + 512;
            if (nb < NN) {
                x0 = xb[(nb + t) * 3 + 0];
                y0 = xb[(nb + t) * 3 + 1];
                z0 = xb[(nb + t) * 3 + 2];
                x1 = xb[(nb + 256 + t) * 3 + 0];
                y1 = xb[(nb + 256 + t) * 3 + 1];
                z1 = xb[(nb + 256 + t) * 3 + 2];
            }
            __syncthreads();   // the ONLY barrier per iteration

            unsigned c0 = 0, c1 = 0, p0 = 0, p1 = 0;
#pragma unroll
            for (int w = 0; w < 8; w++) {
                const unsigned pk = wcnt[sel][w];
                const unsigned a = pk & 0xff, bcnt = (pk >> 8) & 0xff;
                if (w < warp) { p0 += a; p1 += bcnt; }
                c0 += a; c1 += bcnt;
            }
            const int pos0 = cnt + (int)p0 + __popc(m0 & ((1u << lane) - 1u));
            if (h0 && pos0 < NS) sidx[pos0] = base + t;
            const int pos1 = cnt + (int)c0 + (int)p1 + __popc(m1 & ((1u << lane) - 1u));
            if (h1 && pos1 < NS) sidx[pos1] = base + 256 + t;
            cnt += (int)(c0 + c1);   // uniform across block
            sel ^= 1;
            if (cnt >= NS) break;
        }
        __syncthreads();       // sidx visible to all warps

        const int cn = cnt < NS ? cnt : NS;
        if (t < NS) {
            const int first = (cn > 0) ? sidx[0] : NN;
            const bool real = (t < cn);
            const int v = real ? sidx[t] : NN;
            const size_t o = ((size_t)b * PP + p) * NS;
            g_idx[o + t] = v;   // masked (pad -> NN)
            float* out_idx =
                out + (size_t)BB * 131 * PP * NS + (size_t)BB * 3 * PP * NS;
            out_idx[o + t] = (float)(real ? v : first);   // idx0 (pad -> first)
        }
    } else {
        // ---------------- transpose (B,C,N) -> (B,N,C) ----------------
        __shared__ float tile[32][33];
        const int bi2 = bi - NQBLK;
        const int b = bi2 >> 11;          // 2048 blocks per batch
        const int rem = bi2 & 2047;
        const int nBase = (rem >> 2) * 32;
        const int cBase = (rem & 3) * 32;
        const float* fb = f + (size_t)b * CC * NN;
        float* ob = g_ftrans + (size_t)b * NN * CC;
        const int tx = t & 31, ty = t >> 5;  // 32 x 8
#pragma unroll
        for (int i = 0; i < 32; i += 8)
            tile[ty + i][tx] = fb[(size_t)(cBase + ty + i) * NN + nBase + tx];
        __syncthreads();
#pragma unroll
        for (int i = 0; i < 32; i += 8)
            ob[(size_t)(nBase + ty + i) * CC + cBase + tx] = tile[tx][ty + i];
    }
}

// ---------------------------------------------------------------------------
// Kernel 2: gather + group. Block per (chunk-of-64-channels, p, b).
// ---------------------------------------------------------------------------
__global__ void __launch_bounds__(256, 8) gather_kernel(
    const float* __restrict__ xyz, const float* __restrict__ new_xyz,
    float* __restrict__ out) {
    __shared__ float ftile[64 * FST];   // 16.6 KB
    __shared__ int smidx[NS];

    const int chunk = blockIdx.x;       // 0 / 1
    const int p = blockIdx.y;
    const int b = blockIdx.z;
    const int t = threadIdx.x;
    const int warp = t >> 5;
    const int lane = t & 31;

    if (t < NS) smidx[t] = g_idx[((size_t)b * PP + p) * NS + t];
    __syncthreads();

    // gather: 64 rows x 256B contiguous (this chunk's half of each row)
    const float* fb = g_ftrans + (size_t)b * NN * CC + chunk * 64;
#pragma unroll
    for (int s = warp; s < NS; s += 8) {
        const int n = smidx[s];
        if (n < NN) {
            const float* row = fb + (size_t)n * CC + lane;
            ftile[lane * FST + s] = row[0];
            ftile[(lane + 32) * FST + s] = row[32];
        } else {
            ftile[lane * FST + s] = 0.0f;
            ftile[(lane + 32) * FST + s] = 0.0f;
        }
    }
    __syncthreads();

    // write: 64 channels x 64 s, STG.128 along s
    float* nfb = out + (((size_t)b * 131 + 3 + chunk * 64) * PP + p) * NS;
#pragma unroll
    for (int k = 0; k < 4; k++) {
        const int idx = t + 256 * k;     // 0..1023
        const int ch = idx >> 4;         // 0..63
        const int s4 = idx & 15;         // 0..15
        const float* src = &ftile[ch * FST + s4 * 4];
        const float4 v = make_float4(src[0], src[1], src[2], src[3]);
        *(float4*)&nfb[(size_t)ch * PP * NS + s4 * 4] = v;
    }

    // xyz channels: grouped_xyz + xyz_feature (chunk 0 only)
    if (chunk == 0 && t < 192) {
        const int s = t & 63;
        const int c = t >> 6;   // 0..2
        const int n = smidx[s];
        const float q = new_xyz[((size_t)b * PP + p) * 3 + c];
        const float src = (n < NN) ? xyz[((size_t)b * NN + n) * 3 + c] : 1000000.0f;
        const float g = __fadd_rn(src, -q);
        float* gx = out + (size_t)BB * 131 * PP * NS;
        gx[(((size_t)b * 3 + c) * PP + p) * NS + s] = g;
        const float xf = (g > 100000.0f) ? 0.0f : g;
        out[(((size_t)b * 131 + c) * PP + p) * NS + s] = xf / 0.2f;
    }
}

// ---------------------------------------------------------------------------
extern "C" void kernel_launch(void* const* d_in, const int* in_sizes, int n_in,
                              void* d_out, int out_size) {
    const float* xyz      = (const float*)d_in[0];  // (B, N, 3)
    const float* new_xyz  = (const float*)d_in[1];  // (B, P, 3)
    const float* features = (const float*)d_in[2];  // (B, C, N)
    float* out = (float*)d_out;

    prep_kernel<<<NQBLK + NTBLK, 256>>>(features, xyz, new_xyz, out);
    gather_kernel<<<dim3(2, PP, BB), 256>>>(xyz, new_xyz, out);
}

// round 6
// speedup vs baseline: 1.5166x; 1.0806x over previous
#include <cuda_runtime.h>
#include <cuda_bf16.h>

// Problem constants (fixed shapes from reference setup_inputs)
#define BB 4
#define NN 16384
#define PP 1024
#define CC 128
#define NS 64
#define R2 0.04f

#define NQBLK (BB * PP / 4)   // 1024 query blocks (4 centers each)
#define NTBLK (BB * 512 * 4)  // 8192 transpose blocks

// Scratch (allocations forbidden; __device__ globals)
__device__ float g_ftrans[(size_t)BB * NN * CC];   // (B, N, C), 32 MB
__device__ int   g_idx[BB * PP * NS];              // masked gather indices

// Swizzled tile address: 64 s-rows x 64 channels, 16B-group XOR swizzle.
// Column (per-s) STS.128 conflict-free; row (per-ch) LDS.32 ~2-way.
__device__ __forceinline__ int taddr(int s, int ch) {
    return s * 64 + (((ch >> 2) ^ (s & 15)) << 2) + (ch & 3);
}

// ---------------------------------------------------------------------------
// Kernel 1 (union grid): blocks [0, NQBLK) = ball query, block per 4 centers
// (shared xyz scan, packed-u64 SIMD prefix, 1 barrier/iter, prefetched loads).
// Blocks [NQBLK, NQBLK+NTBLK) = feature transpose (B,C,N) -> (B,N,C).
// ---------------------------------------------------------------------------
__global__ void __launch_bounds__(256) prep_kernel(
    const float* __restrict__ f, const float* __restrict__ xyz,
    const float* __restrict__ new_xyz, float* __restrict__ out) {
    const int bi = blockIdx.x;
    const int t = threadIdx.x;
    if (bi < NQBLK) {
        // -------- ball query: 4 centers per block, shared scan --------
        __shared__ int sidx[4][NS];
        __shared__ unsigned long long wcA[2][8], wcB[2][8];
        const int warp = t >> 5;
        const int lane = t & 31;
        const int pb0 = bi * 4;              // first center id (same batch)
        const int b = pb0 >> 10;
        const float* xb = xyz + (size_t)b * NN * 3;

        float qx[4], qy[4], qz[4];
#pragma unroll
        for (int g = 0; g < 4; g++) {
            qx[g] = new_xyz[(size_t)(pb0 + g) * 3 + 0];
            qy[g] = new_xyz[(size_t)(pb0 + g) * 3 + 1];
            qz[g] = new_xyz[(size_t)(pb0 + g) * 3 + 2];
        }

        // prefetch chunk 0: thread owns points t and t+256
        float x0 = xb[t * 3 + 0], y0 = xb[t * 3 + 1], z0 = xb[t * 3 + 2];
        float x1 = xb[(t + 256) * 3 + 0], y1 = xb[(t + 256) * 3 + 1],
              z1 = xb[(t + 256) * 3 + 2];

        int cnt[4] = {0, 0, 0, 0};
        int sel = 0;
        const unsigned lm = (1u << lane) - 1u;
        for (int base = 0; base < NN; base += 512) {
            unsigned m0[4], m1[4];
            bool h0[4], h1[4];
#pragma unroll
            for (int g = 0; g < 4; g++) {
                // JAX f32 rounding: no FMA contraction, left-to-right sum.
                const float ax = __fadd_rn(qx[g], -x0), ay = __fadd_rn(qy[g], -y0),
                            az = __fadd_rn(qz[g], -z0);
                const float d0 = __fadd_rn(
                    __fadd_rn(__fmul_rn(ax, ax), __fmul_rn(ay, ay)),
                    __fmul_rn(az, az));
                const float bx = __fadd_rn(qx[g], -x1), by = __fadd_rn(qy[g], -y1),
                            bz = __fadd_rn(qz[g], -z1);
                const float d1 = __fadd_rn(
                    __fadd_rn(__fmul_rn(bx, bx), __fmul_rn(by, by)),
                    __fmul_rn(bz, bz));
                h0[g] = d0 < R2;
                h1[g] = d1 < R2;
                m0[g] = __ballot_sync(0xffffffffu, h0[g]);
                m1[g] = __ballot_sync(0xffffffffu, h1[g]);
            }
            if (lane == 0) {
                wcA[sel][warp] =
                    (unsigned long long)__popc(m0[0]) |
                    ((unsigned long long)__popc(m1[0]) << 16) |
                    ((unsigned long long)__popc(m0[1]) << 32) |
                    ((unsigned long long)__popc(m1[1]) << 48);
                wcB[sel][warp] =
                    (unsigned long long)__popc(m0[2]) |
                    ((unsigned long long)__popc(m1[2]) << 16) |
                    ((unsigned long long)__popc(m0[3]) << 32) |
                    ((unsigned long long)__popc(m1[3]) << 48);
            }
            // prefetch next chunk BEFORE the barrier
            const int nb = base + 512;
            if (nb < NN) {
                x0 = xb[(nb + t) * 3 + 0];
                y0 = xb[(nb + t) * 3 + 1];
                z0 = xb[(nb + t) * 3 + 2];
                x1 = xb[(nb + 256 + t) * 3 + 0];
                y1 = xb[(nb + 256 + t) * 3 + 1];
                z1 = xb[(nb + 256 + t) * 3 + 2];
            }
            __syncthreads();   // the ONLY barrier per iteration

            unsigned long long preA = 0, totA = 0, preB = 0, totB = 0;
#pragma unroll
            for (int w = 0; w < 8; w++) {
                const unsigned long long va = wcA[sel][w], vb = wcB[sel][w];
                if (w < warp) { preA += va; preB += vb; }
                totA += va; totB += vb;
            }
#pragma unroll
            for (int g = 0; g < 4; g++) {
                const unsigned long long pre = (g < 2) ? preA : preB;
                const unsigned long long tot = (g < 2) ? totA : totB;
                const int sh = (g & 1) * 32;
                const int p0 = (int)((pre >> sh) & 0xffff);
                const int p1 = (int)((pre >> (sh + 16)) & 0xffff);
                const int t0 = (int)((tot >> sh) & 0xffff);
                const int t1 = (int)((tot >> (sh + 16)) & 0xffff);
                const int pos0 = cnt[g] + p0 + __popc(m0[g] & lm);
                if (h0[g] && pos0 < NS) sidx[g][pos0] = base + t;
                const int pos1 = cnt[g] + t0 + p1 + __popc(m1[g] & lm);
                if (h1[g] && pos1 < NS) sidx[g][pos1] = base + 256 + t;
                cnt[g] += t0 + t1;   // uniform across block
            }
            sel ^= 1;
            if (cnt[0] >= NS && cnt[1] >= NS && cnt[2] >= NS && cnt[3] >= NS)
                break;
        }
        __syncthreads();       // sidx visible to all warps

        // ---- outputs: thread t handles center g = t>>6, slot s = t&63 ----
        {
            const int g = t >> 6;
            const int s = t & 63;
            const int cn = cnt[g] < NS ? cnt[g] : NS;
            const int first = (cn > 0) ? sidx[g][0] : NN;
            const bool real = (s < cn);
            const int v = real ? sidx[g][s] : NN;
            const size_t o = (size_t)(pb0 + g) * NS;
            g_idx[o + s] = v;   // masked (pad -> NN)
            float* out_idx =
                out + (size_t)BB * 131 * PP * NS + (size_t)BB * 3 * PP * NS;
            out_idx[o + s] = (float)(real ? v : first);   // idx0 (pad -> first)
        }
    } else {
        // ---------------- transpose (B,C,N) -> (B,N,C) ----------------
        __shared__ float tile[32][33];
        const int bi2 = bi - NQBLK;
        const int b = bi2 >> 11;          // 2048 blocks per batch
        const int rem = bi2 & 2047;
        const int nBase = (rem >> 2) * 32;
        const int cBase = (rem & 3) * 32;
        const float* fb = f + (size_t)b * CC * NN;
        float* ob = g_ftrans + (size_t)b * NN * CC;
        const int tx = t & 31, ty = t >> 5;  // 32 x 8
#pragma unroll
        for (int i = 0; i < 32; i += 8)
            tile[ty + i][tx] = fb[(size_t)(cBase + ty + i) * NN + nBase + tx];
        __syncthreads();
#pragma unroll
        for (int i = 0; i < 32; i += 8)
            ob[(size_t)(nBase + ty + i) * CC + cBase + tx] = tile[tx][ty + i];
    }
}

// ---------------------------------------------------------------------------
// Kernel 2: gather + group. Block per (chunk-of-64-channels, p, b).
// Vectorized: LDG.128 gather -> STS.128 into XOR-swizzled [s][ch] tile ->
// scalar LDS + STG.128 channel-major output.
// ---------------------------------------------------------------------------
__global__ void __launch_bounds__(256, 8) gather_kernel(
    const float* __restrict__ xyz, const float* __restrict__ new_xyz,
    float* __restrict__ out) {
    __shared__ float ftile[64 * 64];    // 16 KB, swizzled
    __shared__ int smidx[NS];

    const int chunk = blockIdx.x;       // 0 / 1
    const int p = blockIdx.y;
    const int b = blockIdx.z;
    const int t = threadIdx.x;
    const int warp = t >> 5;
    const int lane = t & 31;

    if (t < NS) smidx[t] = g_idx[((size_t)b * PP + p) * NS + t];
    __syncthreads();

    // Phase A: gather. Warp handles 2 s-rows per iter (16 lanes x float4 each).
    const float* fb = g_ftrans + (size_t)b * NN * CC + chunk * 64;
    const int c4 = lane & 15;           // 16B group within the row
#pragma unroll
    for (int i = 0; i < 4; i++) {
        const int row = warp * 8 + i * 2 + (lane >> 4);
        const int n = smidx[row];
        float4 v = make_float4(0.f, 0.f, 0.f, 0.f);
        if (n < NN) v = *(const float4*)&fb[(size_t)n * CC + c4 * 4];
        *(float4*)&ftile[row * 64 + ((c4 ^ (row & 15)) << 2)] = v;
    }
    __syncthreads();

    // Phase B: write 64 channels x 64 s, STG.128 along s.
    float* nfb = out + (((size_t)b * 131 + 3 + chunk * 64) * PP + p) * NS;
    const int ch = t >> 2;              // 0..63 (within chunk)
#pragma unroll
    for (int k = 0; k < 4; k++) {
        const int sg = (t & 3) + 4 * k; // 0..15 (group of 4 s)
        float4 v;
        v.x = ftile[taddr(4 * sg + 0, ch)];
        v.y = ftile[taddr(4 * sg + 1, ch)];
        v.z = ftile[taddr(4 * sg + 2, ch)];
        v.w = ftile[taddr(4 * sg + 3, ch)];
        *(float4*)&nfb[(size_t)ch * PP * NS + sg * 4] = v;
    }

    // xyz channels: grouped_xyz + xyz_feature (chunk 0 only)
    if (chunk == 0 && t < 192) {
        const int s = t & 63;
        const int c = t >> 6;   // 0..2
        const int n = smidx[s];
        const float q = new_xyz[((size_t)b * PP + p) * 3 + c];
        const float src = (n < NN) ? xyz[((size_t)b * NN + n) * 3 + c] : 1000000.0f;
        const float g = __fadd_rn(src, -q);
        float* gx = out + (size_t)BB * 131 * PP * NS;
        gx[(((size_t)b * 3 + c) * PP + p) * NS + s] = g;
        const float xf = (g > 100000.0f) ? 0.0f : g;
        out[(((size_t)b * 131 + c) * PP + p) * NS + s] = xf / 0.2f;
    }
}

// ---------------------------------------------------------------------------
extern "C" void kernel_launch(void* const* d_in, const int* in_sizes, int n_in,
                              void* d_out, int out_size) {
    const float* xyz      = (const float*)d_in[0];  // (B, N, 3)
    const float* new_xyz  = (const float*)d_in[1];  // (B, P, 3)
    const float* features = (const float*)d_in[2];  // (B, C, N)
    float* out = (float*)d_out;

    prep_kernel<<<NQBLK + NTBLK, 256>>>(features, xyz, new_xyz, out);
    gather_kernel<<<dim3(2, PP, BB), 256>>>(xyz, new_xyz, out);
}